// round 1
// baseline (speedup 1.0000x reference)
#include <cuda_runtime.h>
#include <math.h>

// Problem shape (fixed by reference: B=4096, D=512)
#define NB 4096
#define ND 512

// GEMM tiling
#define BM 128
#define BN 128
#define BK 16
#define TM 8
#define TN 8

#define RCHUNKS 32           // row chunks for column-LSE partials (4096/128)
#define NEG_BIG (-1e30f)

// ---------------- scratch (device globals; no allocation allowed) ----------
__device__ float g_logits[(size_t)NB * NB];     // 64 MB, fits in L2
__device__ float g_row_lse[NB];
__device__ float g_col_lse[NB];
__device__ float g_diag[NB];
__device__ float g_col_m[RCHUNKS * NB];
__device__ float g_col_s[RCHUNKS * NB];

// ---------------------------------------------------------------------------
// K1: logits = tau * (A @ B^T), A=[NB,ND] row-major, B=[NB,ND] row-major.
// Classic 128x128x16 smem-tiled, 8x8 register-tiled fp32 GEMM.
// ---------------------------------------------------------------------------
__global__ __launch_bounds__(256, 2)
void gemm_tau_kernel(const float* __restrict__ A,
                     const float* __restrict__ Bmat,
                     const float* __restrict__ log_tau)
{
    __shared__ float As[BK][BM];
    __shared__ float Bs[BK][BN];

    const int tid  = threadIdx.x;
    const int row0 = blockIdx.y * BM;
    const int col0 = blockIdx.x * BN;

    // Tile = 128 rows x 16 k = 512 float4 loads per matrix; 256 threads -> 2 each.
    // idx in [0,512): row = idx>>2, k-quad = (idx&3)*4. Second load is row+64.
    const int lr = tid >> 2;
    const int lk = (tid & 3) * 4;

    const int ty = tid >> 4;   // 0..15
    const int tx = tid & 15;   // 0..15

    float acc[TM][TN];
#pragma unroll
    for (int i = 0; i < TM; ++i)
#pragma unroll
        for (int j = 0; j < TN; ++j) acc[i][j] = 0.f;

    for (int k0 = 0; k0 < ND; k0 += BK) {
        float4 a0 = *(const float4*)(A    + (size_t)(row0 + lr)      * ND + k0 + lk);
        float4 a1 = *(const float4*)(A    + (size_t)(row0 + lr + 64) * ND + k0 + lk);
        float4 b0 = *(const float4*)(Bmat + (size_t)(col0 + lr)      * ND + k0 + lk);
        float4 b1 = *(const float4*)(Bmat + (size_t)(col0 + lr + 64) * ND + k0 + lk);

        As[lk + 0][lr]      = a0.x; As[lk + 1][lr]      = a0.y;
        As[lk + 2][lr]      = a0.z; As[lk + 3][lr]      = a0.w;
        As[lk + 0][lr + 64] = a1.x; As[lk + 1][lr + 64] = a1.y;
        As[lk + 2][lr + 64] = a1.z; As[lk + 3][lr + 64] = a1.w;

        Bs[lk + 0][lr]      = b0.x; Bs[lk + 1][lr]      = b0.y;
        Bs[lk + 2][lr]      = b0.z; Bs[lk + 3][lr]      = b0.w;
        Bs[lk + 0][lr + 64] = b1.x; Bs[lk + 1][lr + 64] = b1.y;
        Bs[lk + 2][lr + 64] = b1.z; Bs[lk + 3][lr + 64] = b1.w;

        __syncthreads();

#pragma unroll
        for (int kk = 0; kk < BK; ++kk) {
            float a[TM], b[TN];
            *(float4*)&a[0] = *(const float4*)&As[kk][ty * TM];
            *(float4*)&a[4] = *(const float4*)&As[kk][ty * TM + 4];
            *(float4*)&b[0] = *(const float4*)&Bs[kk][tx * TN];
            *(float4*)&b[4] = *(const float4*)&Bs[kk][tx * TN + 4];
#pragma unroll
            for (int i = 0; i < TM; ++i)
#pragma unroll
                for (int j = 0; j < TN; ++j)
                    acc[i][j] = fmaf(a[i], b[j], acc[i][j]);
        }
        __syncthreads();
    }

    const float tau = fminf(expf(log_tau[0]), 100.0f);

#pragma unroll
    for (int i = 0; i < TM; ++i) {
        const size_t gr = (size_t)(row0 + ty * TM + i);
        float* dst = g_logits + gr * NB + col0 + tx * TN;
        float4 v0 = make_float4(acc[i][0] * tau, acc[i][1] * tau,
                                acc[i][2] * tau, acc[i][3] * tau);
        float4 v1 = make_float4(acc[i][4] * tau, acc[i][5] * tau,
                                acc[i][6] * tau, acc[i][7] * tau);
        *(float4*)(dst)     = v0;
        *(float4*)(dst + 4) = v1;
    }
}

// ---------------------------------------------------------------------------
// K2: per-row logsumexp (two-pass; second read hits L1/L2) + diagonal grab.
// One block per row, 256 threads, float4 reads.
// ---------------------------------------------------------------------------
__global__ __launch_bounds__(256)
void row_lse_kernel()
{
    __shared__ float red[256];
    const int row = blockIdx.x;
    const int tid = threadIdx.x;
    const float* p = g_logits + (size_t)row * NB;

    // pass 1: max
    float tm = NEG_BIG;
    for (int j = tid * 4; j < NB; j += 256 * 4) {
        float4 v = *(const float4*)(p + j);
        tm = fmaxf(tm, fmaxf(fmaxf(v.x, v.y), fmaxf(v.z, v.w)));
    }
    red[tid] = tm;
    __syncthreads();
    for (int s = 128; s > 0; s >>= 1) {
        if (tid < s) red[tid] = fmaxf(red[tid], red[tid + s]);
        __syncthreads();
    }
    const float rmax = red[0];
    __syncthreads();

    // pass 2: sum exp
    float ts = 0.f;
    for (int j = tid * 4; j < NB; j += 256 * 4) {
        float4 v = *(const float4*)(p + j);
        ts += expf(v.x - rmax) + expf(v.y - rmax) +
              expf(v.z - rmax) + expf(v.w - rmax);
    }
    red[tid] = ts;
    __syncthreads();
    for (int s = 128; s > 0; s >>= 1) {
        if (tid < s) red[tid] += red[tid + s];
        __syncthreads();
    }
    if (tid == 0) {
        g_row_lse[row] = rmax + logf(red[0]);
        g_diag[row]    = p[row];
    }
}

// ---------------------------------------------------------------------------
// K3: column-LSE partials. grid = (NB/256, RCHUNKS); thread owns one column
// over a 128-row chunk; reads coalesced across threads. Online (m,s).
// ---------------------------------------------------------------------------
__global__ __launch_bounds__(256)
void col_partial_kernel()
{
    const int col   = blockIdx.x * 256 + threadIdx.x;
    const int chunk = blockIdx.y;
    const int r0 = chunk * (NB / RCHUNKS);
    const int r1 = r0 + (NB / RCHUNKS);

    float m = NEG_BIG, s = 0.f;
    for (int r = r0; r < r1; ++r) {
        const float v = g_logits[(size_t)r * NB + col];
        const float nm = fmaxf(m, v);
        s = s * expf(m - nm) + expf(v - nm);
        m = nm;
    }
    g_col_m[chunk * NB + col] = m;
    g_col_s[chunk * NB + col] = s;
}

// K4: combine column partials -> g_col_lse
__global__ __launch_bounds__(256)
void col_combine_kernel()
{
    const int col = blockIdx.x * 256 + threadIdx.x;
    float m = NEG_BIG;
#pragma unroll
    for (int c = 0; c < RCHUNKS; ++c)
        m = fmaxf(m, g_col_m[c * NB + col]);
    float s = 0.f;
#pragma unroll
    for (int c = 0; c < RCHUNKS; ++c)
        s += g_col_s[c * NB + col] * expf(g_col_m[c * NB + col] - m);
    g_col_lse[col] = m + logf(s);
}

// ---------------------------------------------------------------------------
// K5: final scalar: loss = mean_i( (row_lse[i] + col_lse[i])/2 - diag[i] )
// Double accumulation (values ~1e3, 4096 of them).
// ---------------------------------------------------------------------------
__global__ __launch_bounds__(512)
void final_kernel(float* __restrict__ out)
{
    __shared__ double red[512];
    const int tid = threadIdx.x;
    double acc = 0.0;
    for (int i = tid; i < NB; i += 512)
        acc += 0.5 * ((double)g_row_lse[i] + (double)g_col_lse[i])
               - (double)g_diag[i];
    red[tid] = acc;
    __syncthreads();
    for (int s = 256; s > 0; s >>= 1) {
        if (tid < s) red[tid] += red[tid + s];
        __syncthreads();
    }
    if (tid == 0) out[0] = (float)(red[0] / (double)NB);
}

// ---------------------------------------------------------------------------
extern "C" void kernel_launch(void* const* d_in, const int* in_sizes, int n_in,
                              void* d_out, int out_size)
{
    const float* ftir    = (const float*)d_in[0];   // [4096, 512] f32
    const float* raman   = (const float*)d_in[1];   // [4096, 512] f32
    // d_in[2] = labels (int64) — unused by the reference computation
    const float* log_tau = (const float*)d_in[3];   // scalar f32

    dim3 ggrid(NB / BN, NB / BM);
    gemm_tau_kernel<<<ggrid, 256>>>(ftir, raman, log_tau);
    row_lse_kernel<<<NB, 256>>>();
    col_partial_kernel<<<dim3(NB / 256, RCHUNKS), 256>>>();
    col_combine_kernel<<<NB / 256, 256>>>();
    final_kernel<<<1, 512>>>((float*)d_out);
}

// round 3
// speedup vs baseline: 3.7050x; 3.7050x over previous
#include <cuda_runtime.h>
#include <cuda_bf16.h>
#include <math.h>
#include <stdint.h>

// Problem shape (fixed by reference: B=4096, D=512)
#define NB 4096
#define ND 512

// GEMM tiling
#define BM 128
#define BN 128
#define BK 32
#define NCHUNK (ND / BK)       // 16 k-chunks
#define GTHREADS 256
#define PITCH 40               // smem row pitch in bf16 elems (80B) -> conflict-free ldmatrix

#define RCHUNKS 32
#define NEG_BIG (-1e30f)

// ---------------- scratch (device globals; no allocation allowed) ----------
__device__ __nv_bfloat16 g_a[(size_t)NB * ND];   // bf16 ftir
__device__ __nv_bfloat16 g_b[(size_t)NB * ND];   // bf16 raman
__device__ float g_logits[(size_t)NB * NB];      // 64 MB
__device__ float g_row_lse[NB];
__device__ float g_col_lse[NB];
__device__ float g_diag[NB];
__device__ float g_col_m[RCHUNKS * NB];
__device__ float g_col_s[RCHUNKS * NB];

// ---------------------------------------------------------------------------
// helpers
// ---------------------------------------------------------------------------
__device__ __forceinline__ uint32_t smem_u32(const void* p) {
    uint32_t a;
    asm("{ .reg .u64 t; cvta.to.shared.u64 t, %1; cvt.u32.u64 %0, t; }"
        : "=r"(a) : "l"(p));
    return a;
}

#define CP_ASYNC16(dst_u32, src_ptr) \
    asm volatile("cp.async.cg.shared.global [%0], [%1], 16;" \
        :: "r"(dst_u32), "l"(src_ptr) : "memory")
#define CP_COMMIT() asm volatile("cp.async.commit_group;" ::: "memory")
#define CP_WAIT(n)  asm volatile("cp.async.wait_group %0;" :: "n"(n) : "memory")

#define LDMATRIX_X4(r0, r1, r2, r3, addr) \
    asm volatile("ldmatrix.sync.aligned.m8n8.x4.shared.b16 {%0,%1,%2,%3}, [%4];" \
        : "=r"(r0), "=r"(r1), "=r"(r2), "=r"(r3) : "r"(addr))

#define MMA_16816(d, a, b) \
    asm volatile("mma.sync.aligned.m16n8k16.row.col.f32.bf16.bf16.f32 " \
        "{%0,%1,%2,%3}, {%4,%5,%6,%7}, {%8,%9}, {%0,%1,%2,%3};" \
        : "+f"((d)[0]), "+f"((d)[1]), "+f"((d)[2]), "+f"((d)[3]) \
        : "r"((a)[0]), "r"((a)[1]), "r"((a)[2]), "r"((a)[3]), \
          "r"((b)[0]), "r"((b)[1]))

// ---------------------------------------------------------------------------
// K0: fp32 -> bf16 conversion of both inputs
// ---------------------------------------------------------------------------
__global__ __launch_bounds__(256)
void convert_kernel(const float* __restrict__ srcA, const float* __restrict__ srcB)
{
    const float* src = blockIdx.y ? srcB : srcA;
    __nv_bfloat16* dst = blockIdx.y ? g_b : g_a;
    size_t i = ((size_t)blockIdx.x * 256 + threadIdx.x) * 8;
    float4 v0 = *(const float4*)(src + i);
    float4 v1 = *(const float4*)(src + i + 4);
    __nv_bfloat162 o[4];
    o[0] = __float22bfloat162_rn(make_float2(v0.x, v0.y));
    o[1] = __float22bfloat162_rn(make_float2(v0.z, v0.w));
    o[2] = __float22bfloat162_rn(make_float2(v1.x, v1.y));
    o[3] = __float22bfloat162_rn(make_float2(v1.z, v1.w));
    *(uint4*)(dst + i) = *(const uint4*)o;
}

// ---------------------------------------------------------------------------
// K1: logits = tau * (A @ B^T) via mma.sync bf16 (HMMA), 128x128 per CTA,
// 8 warps (4M x 2N), warp tile 32x64, cp.async double-buffered K=32 chunks.
// ---------------------------------------------------------------------------
__global__ __launch_bounds__(GTHREADS)
void gemm_bf16_kernel(const float* __restrict__ log_tau)
{
    __shared__ __nv_bfloat16 sA[2][BM * PITCH];
    __shared__ __nv_bfloat16 sB[2][BN * PITCH];

    const int tid  = threadIdx.x;
    const int wid  = tid >> 5;
    const int lane = tid & 31;
    const int wm   = wid & 3;     // warp M index (0..3)
    const int wn   = wid >> 2;    // warp N index (0..1)
    const int row0 = blockIdx.y * BM;
    const int col0 = blockIdx.x * BN;

    const uint32_t sA0 = smem_u32(&sA[0][0]);
    const uint32_t sB0 = smem_u32(&sB[0][0]);

    // producer mapping: 128 rows x 4 segs of 16B; 256 threads -> 2 rows apart 64
    const int pr  = tid >> 2;     // 0..63
    const int seg = tid & 3;

    // ldmatrix address components (in bytes, relative to buffer base)
    // A quad mapping: row += ((lane>>3)&1)*8 + (lane&7); kofs = (lane>>4)*8
    const uint32_t aoff =
        (uint32_t)((wm * 32 + ((lane >> 3) & 1) * 8 + (lane & 7)) * PITCH * 2
                   + (lane >> 4) * 16);
    // B quad mapping: row += (lane>>4)*8 + (lane&7); kofs = ((lane>>3)&1)*8
    const uint32_t boff =
        (uint32_t)((wn * 64 + (lane >> 4) * 8 + (lane & 7)) * PITCH * 2
                   + ((lane >> 3) & 1) * 16);

    float acc[2][8][4];
#pragma unroll
    for (int i = 0; i < 2; ++i)
#pragma unroll
        for (int j = 0; j < 8; ++j)
#pragma unroll
            for (int q = 0; q < 4; ++q) acc[i][j][q] = 0.f;

    // --- prefetch chunk 0
#pragma unroll
    for (int t = 0; t < 2; ++t) {
        const int r = pr + t * 64;
        CP_ASYNC16(sA0 + (r * PITCH + seg * 8) * 2,
                   g_a + (size_t)(row0 + r) * ND + seg * 8);
        CP_ASYNC16(sB0 + (r * PITCH + seg * 8) * 2,
                   g_b + (size_t)(col0 + r) * ND + seg * 8);
    }
    CP_COMMIT();

    for (int c = 0; c < NCHUNK; ++c) {
        const int cur = c & 1;
        if (c + 1 < NCHUNK) {
            const int nxt = cur ^ 1;
            const int k0 = (c + 1) * BK;
            const uint32_t dA = sA0 + nxt * (BM * PITCH * 2);
            const uint32_t dB = sB0 + nxt * (BN * PITCH * 2);
#pragma unroll
            for (int t = 0; t < 2; ++t) {
                const int r = pr + t * 64;
                CP_ASYNC16(dA + (r * PITCH + seg * 8) * 2,
                           g_a + (size_t)(row0 + r) * ND + k0 + seg * 8);
                CP_ASYNC16(dB + (r * PITCH + seg * 8) * 2,
                           g_b + (size_t)(col0 + r) * ND + k0 + seg * 8);
            }
            CP_COMMIT();
            CP_WAIT(1);
        } else {
            CP_WAIT(0);
        }
        __syncthreads();

        const uint32_t bufA = sA0 + cur * (BM * PITCH * 2) + aoff;
        const uint32_t bufB = sB0 + cur * (BN * PITCH * 2) + boff;

#pragma unroll
        for (int ks = 0; ks < 2; ++ks) {        // two k16 steps per chunk
            const uint32_t kb = ks * 32;        // 16 halves = 32 bytes
            uint32_t a[2][4], b[4][4];
#pragma unroll
            for (int mi = 0; mi < 2; ++mi)
                LDMATRIX_X4(a[mi][0], a[mi][1], a[mi][2], a[mi][3],
                            bufA + mi * (16 * PITCH * 2) + kb);
#pragma unroll
            for (int nj = 0; nj < 4; ++nj)
                LDMATRIX_X4(b[nj][0], b[nj][1], b[nj][2], b[nj][3],
                            bufB + nj * (16 * PITCH * 2) + kb);
#pragma unroll
            for (int mi = 0; mi < 2; ++mi)
#pragma unroll
                for (int nj = 0; nj < 4; ++nj) {
                    MMA_16816(acc[mi][nj * 2],     a[mi], &b[nj][0]);
                    MMA_16816(acc[mi][nj * 2 + 1], a[mi], &b[nj][2]);
                }
        }
        __syncthreads();
    }

    const float tau = fminf(expf(log_tau[0]), 100.0f);
    const int lrow = lane >> 2;
    const int lcol = (lane & 3) * 2;

#pragma unroll
    for (int mi = 0; mi < 2; ++mi) {
        const int grow = row0 + wm * 32 + mi * 16 + lrow;
#pragma unroll
        for (int ni = 0; ni < 8; ++ni) {
            const int gcol = col0 + wn * 64 + ni * 8 + lcol;
            float* p0 = g_logits + (size_t)grow * NB + gcol;
            float* p1 = p0 + (size_t)8 * NB;
            float2 v0 = make_float2(acc[mi][ni][0] * tau, acc[mi][ni][1] * tau);
            float2 v1 = make_float2(acc[mi][ni][2] * tau, acc[mi][ni][3] * tau);
            *(float2*)p0 = v0;
            *(float2*)p1 = v1;
        }
    }
}

// ---------------------------------------------------------------------------
// K2: per-row logsumexp + diagonal grab.
// ---------------------------------------------------------------------------
__global__ __launch_bounds__(256)
void row_lse_kernel()
{
    __shared__ float red[256];
    const int row = blockIdx.x;
    const int tid = threadIdx.x;
    const float* p = g_logits + (size_t)row * NB;

    float tm = NEG_BIG;
    for (int j = tid * 4; j < NB; j += 256 * 4) {
        float4 v = *(const float4*)(p + j);
        tm = fmaxf(tm, fmaxf(fmaxf(v.x, v.y), fmaxf(v.z, v.w)));
    }
    red[tid] = tm;
    __syncthreads();
    for (int s = 128; s > 0; s >>= 1) {
        if (tid < s) red[tid] = fmaxf(red[tid], red[tid + s]);
        __syncthreads();
    }
    const float rmax = red[0];
    __syncthreads();

    float ts = 0.f;
    for (int j = tid * 4; j < NB; j += 256 * 4) {
        float4 v = *(const float4*)(p + j);
        ts += expf(v.x - rmax) + expf(v.y - rmax) +
              expf(v.z - rmax) + expf(v.w - rmax);
    }
    red[tid] = ts;
    __syncthreads();
    for (int s = 128; s > 0; s >>= 1) {
        if (tid < s) red[tid] += red[tid + s];
        __syncthreads();
    }
    if (tid == 0) {
        g_row_lse[row] = rmax + logf(red[0]);
        g_diag[row]    = p[row];
    }
}

// ---------------------------------------------------------------------------
// K3: column-LSE partials over 128-row chunks.
// ---------------------------------------------------------------------------
__global__ __launch_bounds__(256)
void col_partial_kernel()
{
    const int col   = blockIdx.x * 256 + threadIdx.x;
    const int chunk = blockIdx.y;
    const int r0 = chunk * (NB / RCHUNKS);
    const int r1 = r0 + (NB / RCHUNKS);

    float m = NEG_BIG, s = 0.f;
    for (int r = r0; r < r1; ++r) {
        const float v = g_logits[(size_t)r * NB + col];
        const float nm = fmaxf(m, v);
        s = s * expf(m - nm) + expf(v - nm);
        m = nm;
    }
    g_col_m[chunk * NB + col] = m;
    g_col_s[chunk * NB + col] = s;
}

__global__ __launch_bounds__(256)
void col_combine_kernel()
{
    const int col = blockIdx.x * 256 + threadIdx.x;
    float m = NEG_BIG;
#pragma unroll
    for (int c = 0; c < RCHUNKS; ++c)
        m = fmaxf(m, g_col_m[c * NB + col]);
    float s = 0.f;
#pragma unroll
    for (int c = 0; c < RCHUNKS; ++c)
        s += g_col_s[c * NB + col] * expf(g_col_m[c * NB + col] - m);
    g_col_lse[col] = m + logf(s);
}

// ---------------------------------------------------------------------------
// K5: final scalar
// ---------------------------------------------------------------------------
__global__ __launch_bounds__(512)
void final_kernel(float* __restrict__ out)
{
    __shared__ double red[512];
    const int tid = threadIdx.x;
    double acc = 0.0;
    for (int i = tid; i < NB; i += 512)
        acc += 0.5 * ((double)g_row_lse[i] + (double)g_col_lse[i])
               - (double)g_diag[i];
    red[tid] = acc;
    __syncthreads();
    for (int s = 256; s > 0; s >>= 1) {
        if (tid < s) red[tid] += red[tid + s];
        __syncthreads();
    }
    if (tid == 0) out[0] = (float)(red[0] / (double)NB);
}

// ---------------------------------------------------------------------------
extern "C" void kernel_launch(void* const* d_in, const int* in_sizes, int n_in,
                              void* d_out, int out_size)
{
    const float* ftir    = (const float*)d_in[0];   // [4096, 512] f32
    const float* raman   = (const float*)d_in[1];   // [4096, 512] f32
    // d_in[2] = labels (int64) — unused
    const float* log_tau = (const float*)d_in[3];   // scalar f32

    convert_kernel<<<dim3(NB * ND / (256 * 8), 2), 256>>>(ftir, raman);
    gemm_bf16_kernel<<<dim3(NB / BN, NB / BM), GTHREADS>>>(log_tau);
    row_lse_kernel<<<NB, 256>>>();
    col_partial_kernel<<<dim3(NB / 256, RCHUNKS), 256>>>();
    col_combine_kernel<<<NB / 256, 256>>>();
    final_kernel<<<1, 512>>>((float*)d_out);
}

// round 4
// speedup vs baseline: 5.2872x; 1.4271x over previous
#include <cuda_runtime.h>
#include <cuda_bf16.h>
#include <math.h>
#include <stdint.h>

// Problem shape (fixed by reference: B=4096, D=512)
#define NB 4096
#define ND 512

// GEMM tiling
#define BM 128
#define BN 128
#define BK 32
#define NCHUNK (ND / BK)       // 16 k-chunks
#define GTHREADS 256
#define PITCH 40               // smem row pitch in bf16 elems (80B) -> conflict-free ldmatrix

#define NBLK (NB / BM)         // 32 tile blocks per dimension
#define NEG_BIG (-1e30f)

// ---------------- scratch (device globals; no allocation allowed) ----------
__device__ __nv_bfloat16 g_a[(size_t)NB * ND];   // bf16 ftir
__device__ __nv_bfloat16 g_b[(size_t)NB * ND];   // bf16 raman
__device__ float g_rp_m[NBLK * NB];              // row partial max   [colblk][row]
__device__ float g_rp_s[NBLK * NB];              // row partial sum
__device__ float g_cp_m[NBLK * NB];              // col partial max   [rowblk][col]
__device__ float g_cp_s[NBLK * NB];              // col partial sum
__device__ float g_row_lse[NB];
__device__ float g_col_lse[NB];
__device__ float g_diag[NB];

// ---------------------------------------------------------------------------
// helpers
// ---------------------------------------------------------------------------
__device__ __forceinline__ uint32_t smem_u32(const void* p) {
    uint32_t a;
    asm("{ .reg .u64 t; cvta.to.shared.u64 t, %1; cvt.u32.u64 %0, t; }"
        : "=r"(a) : "l"(p));
    return a;
}

#define CP_ASYNC16(dst_u32, src_ptr) \
    asm volatile("cp.async.cg.shared.global [%0], [%1], 16;" \
        :: "r"(dst_u32), "l"(src_ptr) : "memory")
#define CP_COMMIT() asm volatile("cp.async.commit_group;" ::: "memory")
#define CP_WAIT(n)  asm volatile("cp.async.wait_group %0;" :: "n"(n) : "memory")

#define LDMATRIX_X4(r0, r1, r2, r3, addr) \
    asm volatile("ldmatrix.sync.aligned.m8n8.x4.shared.b16 {%0,%1,%2,%3}, [%4];" \
        : "=r"(r0), "=r"(r1), "=r"(r2), "=r"(r3) : "r"(addr))

#define MMA_16816(d, a, b) \
    asm volatile("mma.sync.aligned.m16n8k16.row.col.f32.bf16.bf16.f32 " \
        "{%0,%1,%2,%3}, {%4,%5,%6,%7}, {%8,%9}, {%0,%1,%2,%3};" \
        : "+f"((d)[0]), "+f"((d)[1]), "+f"((d)[2]), "+f"((d)[3]) \
        : "r"((a)[0]), "r"((a)[1]), "r"((a)[2]), "r"((a)[3]), \
          "r"((b)[0]), "r"((b)[1]))

// ---------------------------------------------------------------------------
// K0: fp32 -> bf16 conversion of both inputs
// ---------------------------------------------------------------------------
__global__ __launch_bounds__(256)
void convert_kernel(const float* __restrict__ srcA, const float* __restrict__ srcB)
{
    const float* src = blockIdx.y ? srcB : srcA;
    __nv_bfloat16* dst = blockIdx.y ? g_b : g_a;
    size_t i = ((size_t)blockIdx.x * 256 + threadIdx.x) * 8;
    float4 v0 = *(const float4*)(src + i);
    float4 v1 = *(const float4*)(src + i + 4);
    __nv_bfloat162 o[4];
    o[0] = __float22bfloat162_rn(make_float2(v0.x, v0.y));
    o[1] = __float22bfloat162_rn(make_float2(v0.z, v0.w));
    o[2] = __float22bfloat162_rn(make_float2(v1.x, v1.y));
    o[3] = __float22bfloat162_rn(make_float2(v1.z, v1.w));
    *(uint4*)(dst + i) = *(const uint4*)o;
}

// ---------------------------------------------------------------------------
// K1: fused GEMM + split-softmax partials.
// logits tile (128x128) = tau * A @ B^T lives only in registers.
// Per CTA outputs: row (m,s) over its 128 cols; col (m,s) over its 128 rows;
// diag values on bx==by tiles. No 64MB logits materialization.
// ---------------------------------------------------------------------------
__global__ __launch_bounds__(GTHREADS)
void gemm_fused_kernel(const float* __restrict__ log_tau)
{
    __shared__ __nv_bfloat16 sA[2][BM * PITCH];
    __shared__ __nv_bfloat16 sB[2][BN * PITCH];
    __shared__ float sm_rm[2][BM], sm_rs[2][BM];   // [wn][row_local]
    __shared__ float sm_cm[4][BN], sm_cs[4][BN];   // [wm][col_local]

    const int tid  = threadIdx.x;
    const int wid  = tid >> 5;
    const int lane = tid & 31;
    const int wm   = wid & 3;     // warp M index (0..3)
    const int wn   = wid >> 2;    // warp N index (0..1)
    const int bx   = blockIdx.x;
    const int by   = blockIdx.y;
    const int row0 = by * BM;
    const int col0 = bx * BN;

    const uint32_t sA0 = smem_u32(&sA[0][0]);
    const uint32_t sB0 = smem_u32(&sB[0][0]);

    const int pr  = tid >> 2;     // 0..63
    const int seg = tid & 3;

    const uint32_t aoff =
        (uint32_t)((wm * 32 + ((lane >> 3) & 1) * 8 + (lane & 7)) * PITCH * 2
                   + (lane >> 4) * 16);
    const uint32_t boff =
        (uint32_t)((wn * 64 + (lane >> 4) * 8 + (lane & 7)) * PITCH * 2
                   + ((lane >> 3) & 1) * 16);

    float acc[2][8][4];
#pragma unroll
    for (int i = 0; i < 2; ++i)
#pragma unroll
        for (int j = 0; j < 8; ++j)
#pragma unroll
            for (int q = 0; q < 4; ++q) acc[i][j][q] = 0.f;

    // --- prefetch chunk 0
#pragma unroll
    for (int t = 0; t < 2; ++t) {
        const int r = pr + t * 64;
        CP_ASYNC16(sA0 + (r * PITCH + seg * 8) * 2,
                   g_a + (size_t)(row0 + r) * ND + seg * 8);
        CP_ASYNC16(sB0 + (r * PITCH + seg * 8) * 2,
                   g_b + (size_t)(col0 + r) * ND + seg * 8);
    }
    CP_COMMIT();

    for (int c = 0; c < NCHUNK; ++c) {
        const int cur = c & 1;
        if (c + 1 < NCHUNK) {
            const int nxt = cur ^ 1;
            const int k0 = (c + 1) * BK;
            const uint32_t dA = sA0 + nxt * (BM * PITCH * 2);
            const uint32_t dB = sB0 + nxt * (BN * PITCH * 2);
#pragma unroll
            for (int t = 0; t < 2; ++t) {
                const int r = pr + t * 64;
                CP_ASYNC16(dA + (r * PITCH + seg * 8) * 2,
                           g_a + (size_t)(row0 + r) * ND + k0 + seg * 8);
                CP_ASYNC16(dB + (r * PITCH + seg * 8) * 2,
                           g_b + (size_t)(col0 + r) * ND + k0 + seg * 8);
            }
            CP_COMMIT();
            CP_WAIT(1);
        } else {
            CP_WAIT(0);
        }
        __syncthreads();

        const uint32_t bufA = sA0 + cur * (BM * PITCH * 2) + aoff;
        const uint32_t bufB = sB0 + cur * (BN * PITCH * 2) + boff;

#pragma unroll
        for (int ks = 0; ks < 2; ++ks) {        // two k16 steps per chunk
            const uint32_t kb = ks * 32;
            uint32_t a[2][4], b[4][4];
#pragma unroll
            for (int mi = 0; mi < 2; ++mi)
                LDMATRIX_X4(a[mi][0], a[mi][1], a[mi][2], a[mi][3],
                            bufA + mi * (16 * PITCH * 2) + kb);
#pragma unroll
            for (int nj = 0; nj < 4; ++nj)
                LDMATRIX_X4(b[nj][0], b[nj][1], b[nj][2], b[nj][3],
                            bufB + nj * (16 * PITCH * 2) + kb);
#pragma unroll
            for (int mi = 0; mi < 2; ++mi)
#pragma unroll
                for (int nj = 0; nj < 4; ++nj) {
                    MMA_16816(acc[mi][nj * 2],     a[mi], &b[nj][0]);
                    MMA_16816(acc[mi][nj * 2 + 1], a[mi], &b[nj][2]);
                }
        }
        __syncthreads();
    }

    // ---------------- fused epilogue ----------------
    const float tau = fminf(expf(log_tau[0]), 100.0f);
#pragma unroll
    for (int mi = 0; mi < 2; ++mi)
#pragma unroll
        for (int nj = 0; nj < 8; ++nj)
#pragma unroll
            for (int q = 0; q < 4; ++q) acc[mi][nj][q] *= tau;

    const int lrow = lane >> 2;
    const int lcol = (lane & 3) * 2;

    // diag extraction (only on diagonal tiles)
    if (bx == by) {
#pragma unroll
        for (int mi = 0; mi < 2; ++mi)
#pragma unroll
            for (int nj = 0; nj < 8; ++nj)
#pragma unroll
                for (int q = 0; q < 4; ++q) {
                    const int rl = wm * 32 + mi * 16 + ((q >> 1) << 3) + lrow;
                    const int cl = wn * 64 + nj * 8 + lcol + (q & 1);
                    if (rl == cl) g_diag[row0 + rl] = acc[mi][nj][q];
                }
    }

    // --- row partials: max+sum over this warp's 64 columns
#pragma unroll
    for (int mi = 0; mi < 2; ++mi)
#pragma unroll
        for (int h = 0; h < 2; ++h) {
            float m = NEG_BIG;
#pragma unroll
            for (int nj = 0; nj < 8; ++nj)
                m = fmaxf(m, fmaxf(acc[mi][nj][h * 2], acc[mi][nj][h * 2 + 1]));
            m = fmaxf(m, __shfl_xor_sync(0xffffffffu, m, 1));
            m = fmaxf(m, __shfl_xor_sync(0xffffffffu, m, 2));
            float s = 0.f;
#pragma unroll
            for (int nj = 0; nj < 8; ++nj)
                s += __expf(acc[mi][nj][h * 2] - m) +
                     __expf(acc[mi][nj][h * 2 + 1] - m);
            s += __shfl_xor_sync(0xffffffffu, s, 1);
            s += __shfl_xor_sync(0xffffffffu, s, 2);
            if ((lane & 3) == 0) {
                const int r = wm * 32 + mi * 16 + h * 8 + lrow;
                sm_rm[wn][r] = m;
                sm_rs[wn][r] = s;
            }
        }

    // --- col partials: max+sum over this warp's 32 rows
#pragma unroll
    for (int nj = 0; nj < 8; ++nj)
#pragma unroll
        for (int cc = 0; cc < 2; ++cc) {
            const float v0 = acc[0][nj][cc], v1 = acc[0][nj][2 + cc];
            const float v2 = acc[1][nj][cc], v3 = acc[1][nj][2 + cc];
            float m = fmaxf(fmaxf(v0, v1), fmaxf(v2, v3));
            m = fmaxf(m, __shfl_xor_sync(0xffffffffu, m, 4));
            m = fmaxf(m, __shfl_xor_sync(0xffffffffu, m, 8));
            m = fmaxf(m, __shfl_xor_sync(0xffffffffu, m, 16));
            float s = __expf(v0 - m) + __expf(v1 - m) +
                      __expf(v2 - m) + __expf(v3 - m);
            s += __shfl_xor_sync(0xffffffffu, s, 4);
            s += __shfl_xor_sync(0xffffffffu, s, 8);
            s += __shfl_xor_sync(0xffffffffu, s, 16);
            if (lane < 4) {
                const int cl = wn * 64 + nj * 8 + (lane & 3) * 2 + cc;
                sm_cm[wm][cl] = m;
                sm_cs[wm][cl] = s;
            }
        }

    __syncthreads();

    if (tid < BM) {
        // combine the two wn warps -> row partial for this tile
        const float m0 = sm_rm[0][tid], m1 = sm_rm[1][tid];
        const float m = fmaxf(m0, m1);
        const float s = sm_rs[0][tid] * __expf(m0 - m) +
                        sm_rs[1][tid] * __expf(m1 - m);
        g_rp_m[bx * NB + row0 + tid] = m;
        g_rp_s[bx * NB + row0 + tid] = s;

        // combine the four wm warps -> col partial for this tile
        float cm = NEG_BIG;
#pragma unroll
        for (int w = 0; w < 4; ++w) cm = fmaxf(cm, sm_cm[w][tid]);
        float cs = 0.f;
#pragma unroll
        for (int w = 0; w < 4; ++w) cs += sm_cs[w][tid] * __expf(sm_cm[w][tid] - cm);
        g_cp_m[by * NB + col0 + tid] = cm;
        g_cp_s[by * NB + col0 + tid] = cs;
    }
}

// ---------------------------------------------------------------------------
// K2: combine partials -> per-row / per-col LSE. blockIdx.y selects direction.
// ---------------------------------------------------------------------------
__global__ __launch_bounds__(256)
void combine_kernel()
{
    const int i = blockIdx.x * 256 + threadIdx.x;
    const float* Pm = blockIdx.y ? g_cp_m : g_rp_m;
    const float* Ps = blockIdx.y ? g_cp_s : g_rp_s;
    float* out      = blockIdx.y ? g_col_lse : g_row_lse;

    float m = NEG_BIG;
#pragma unroll
    for (int c = 0; c < NBLK; ++c)
        m = fmaxf(m, Pm[c * NB + i]);
    float s = 0.f;
#pragma unroll
    for (int c = 0; c < NBLK; ++c)
        s += Ps[c * NB + i] * __expf(Pm[c * NB + i] - m);
    out[i] = m + logf(s);
}

// ---------------------------------------------------------------------------
// K3: final scalar
// ---------------------------------------------------------------------------
__global__ __launch_bounds__(512)
void final_kernel(float* __restrict__ out)
{
    __shared__ double red[512];
    const int tid = threadIdx.x;
    double acc = 0.0;
    for (int i = tid; i < NB; i += 512)
        acc += 0.5 * ((double)g_row_lse[i] + (double)g_col_lse[i])
               - (double)g_diag[i];
    red[tid] = acc;
    __syncthreads();
    for (int s = 256; s > 0; s >>= 1) {
        if (tid < s) red[tid] += red[tid + s];
        __syncthreads();
    }
    if (tid == 0) out[0] = (float)(red[0] / (double)NB);
}

// ---------------------------------------------------------------------------
extern "C" void kernel_launch(void* const* d_in, const int* in_sizes, int n_in,
                              void* d_out, int out_size)
{
    const float* ftir    = (const float*)d_in[0];   // [4096, 512] f32
    const float* raman   = (const float*)d_in[1];   // [4096, 512] f32
    // d_in[2] = labels (int64) — unused
    const float* log_tau = (const float*)d_in[3];   // scalar f32

    convert_kernel<<<dim3(NB * ND / (256 * 8), 2), 256>>>(ftir, raman);
    gemm_fused_kernel<<<dim3(NB / BN, NB / BM), GTHREADS>>>(log_tau);
    combine_kernel<<<dim3(NB / 256, 2), 256>>>();
    final_kernel<<<1, 512>>>((float*)d_out);
}

// round 5
// speedup vs baseline: 6.3683x; 1.2045x over previous
#include <cuda_runtime.h>
#include <cuda_bf16.h>
#include <math.h>
#include <stdint.h>

// Problem shape (fixed by reference: B=4096, D=512)
#define NB 4096
#define ND 512

// GEMM tiling
#define BM 128
#define BN 128
#define BK 64
#define NCHUNK (ND / BK)       // 8 k-chunks
#define GTHREADS 256
#define PITCH 72               // smem row pitch in bf16 elems (144B) -> conflict-free ldmatrix
#define ROWB (PITCH * 2)       // 144 bytes per smem row
#define STAGE_A (BM * ROWB)    // 18432 B
#define STAGE_B (BN * ROWB)    // 18432 B
#define SM_DYN (2 * (STAGE_A + STAGE_B))   // 73728 B dynamic smem

#define NBLK (NB / BM)         // 32 tile blocks per dimension
#define NEG_BIG (-1e30f)

// ---------------- scratch (device globals; no allocation allowed) ----------
__device__ __nv_bfloat16 g_a[(size_t)NB * ND];   // bf16 ftir
__device__ __nv_bfloat16 g_b[(size_t)NB * ND];   // bf16 raman
__device__ float g_rp_m[NBLK * NB];              // row partial max   [colblk][row]
__device__ float g_rp_s[NBLK * NB];              // row partial sum
__device__ float g_cp_m[NBLK * NB];              // col partial max   [rowblk][col]
__device__ float g_cp_s[NBLK * NB];              // col partial sum
__device__ float g_diag[NB];
__device__ double g_part[32];
__device__ int    g_ticket;                      // zero-init; self-resetting

// ---------------------------------------------------------------------------
// helpers
// ---------------------------------------------------------------------------
__device__ __forceinline__ uint32_t smem_u32(const void* p) {
    uint32_t a;
    asm("{ .reg .u64 t; cvta.to.shared.u64 t, %1; cvt.u32.u64 %0, t; }"
        : "=r"(a) : "l"(p));
    return a;
}

#define CP_ASYNC16(dst_u32, src_ptr) \
    asm volatile("cp.async.cg.shared.global [%0], [%1], 16;" \
        :: "r"(dst_u32), "l"(src_ptr) : "memory")
#define CP_COMMIT() asm volatile("cp.async.commit_group;" ::: "memory")
#define CP_WAIT(n)  asm volatile("cp.async.wait_group %0;" :: "n"(n) : "memory")

#define LDMATRIX_X4(r0, r1, r2, r3, addr) \
    asm volatile("ldmatrix.sync.aligned.m8n8.x4.shared.b16 {%0,%1,%2,%3}, [%4];" \
        : "=r"(r0), "=r"(r1), "=r"(r2), "=r"(r3) : "r"(addr))

#define MMA_16816(d, a, b) \
    asm volatile("mma.sync.aligned.m16n8k16.row.col.f32.bf16.bf16.f32 " \
        "{%0,%1,%2,%3}, {%4,%5,%6,%7}, {%8,%9}, {%0,%1,%2,%3};" \
        : "+f"((d)[0]), "+f"((d)[1]), "+f"((d)[2]), "+f"((d)[3]) \
        : "r"((a)[0]), "r"((a)[1]), "r"((a)[2]), "r"((a)[3]), \
          "r"((b)[0]), "r"((b)[1]))

// ---------------------------------------------------------------------------
// K0: fp32 -> bf16 conversion of both inputs
// ---------------------------------------------------------------------------
__global__ __launch_bounds__(256)
void convert_kernel(const float* __restrict__ srcA, const float* __restrict__ srcB)
{
    const float* src = blockIdx.y ? srcB : srcA;
    __nv_bfloat16* dst = blockIdx.y ? g_b : g_a;
    size_t i = ((size_t)blockIdx.x * 256 + threadIdx.x) * 8;
    float4 v0 = *(const float4*)(src + i);
    float4 v1 = *(const float4*)(src + i + 4);
    __nv_bfloat162 o[4];
    o[0] = __float22bfloat162_rn(make_float2(v0.x, v0.y));
    o[1] = __float22bfloat162_rn(make_float2(v0.z, v0.w));
    o[2] = __float22bfloat162_rn(make_float2(v1.x, v1.y));
    o[3] = __float22bfloat162_rn(make_float2(v1.z, v1.w));
    *(uint4*)(dst + i) = *(const uint4*)o;
}

// ---------------------------------------------------------------------------
// K1: fused GEMM + split-softmax partials.
// 128x128 logits tile in registers; BK=64 double-buffered cp.async pipeline
// with ONE __syncthreads per k-iteration.
// ---------------------------------------------------------------------------
__global__ __launch_bounds__(GTHREADS, 2)
void gemm_fused_kernel(const float* __restrict__ log_tau)
{
    extern __shared__ char dyn[];
    __shared__ float sm_rm[2][BM], sm_rs[2][BM];   // [wn][row_local]
    __shared__ float sm_cm[4][BN], sm_cs[4][BN];   // [wm][col_local]

    const int tid  = threadIdx.x;
    const int wid  = tid >> 5;
    const int lane = tid & 31;
    const int wm   = wid & 3;     // warp M index (0..3)
    const int wn   = wid >> 2;    // warp N index (0..1)
    const int bx   = blockIdx.x;
    const int by   = blockIdx.y;
    const int row0 = by * BM;
    const int col0 = bx * BN;

    const uint32_t sA0 = smem_u32(dyn);
    const uint32_t sB0 = sA0 + 2 * STAGE_A;

    // producer mapping: 128 rows x 8 segs of 16B; 256 threads -> 4 rows each
    const int pr  = tid >> 3;     // 0..31
    const int seg = tid & 7;      // 0..7

    const uint32_t aoff =
        (uint32_t)((wm * 32 + ((lane >> 3) & 1) * 8 + (lane & 7)) * ROWB
                   + (lane >> 4) * 16);
    const uint32_t boff =
        (uint32_t)((wn * 64 + (lane >> 4) * 8 + (lane & 7)) * ROWB
                   + ((lane >> 3) & 1) * 16);

    float acc[2][8][4];
#pragma unroll
    for (int i = 0; i < 2; ++i)
#pragma unroll
        for (int j = 0; j < 8; ++j)
#pragma unroll
            for (int q = 0; q < 4; ++q) acc[i][j][q] = 0.f;

    // --- prefetch chunk 0
#pragma unroll
    for (int t = 0; t < 4; ++t) {
        const int r = t * 32 + pr;
        CP_ASYNC16(sA0 + r * ROWB + seg * 16,
                   g_a + (size_t)(row0 + r) * ND + seg * 8);
        CP_ASYNC16(sB0 + r * ROWB + seg * 16,
                   g_b + (size_t)(col0 + r) * ND + seg * 8);
    }
    CP_COMMIT();

    for (int c = 0; c < NCHUNK; ++c) {
        const int cur = c & 1;
        CP_WAIT(0);            // loads for chunk c complete
        __syncthreads();       // visible to all; all warps done with buffer cur^1

        if (c + 1 < NCHUNK) {
            const int nxt = cur ^ 1;
            const int k0 = (c + 1) * BK;
            const uint32_t dA = sA0 + nxt * STAGE_A;
            const uint32_t dB = sB0 + nxt * STAGE_B;
#pragma unroll
            for (int t = 0; t < 4; ++t) {
                const int r = t * 32 + pr;
                CP_ASYNC16(dA + r * ROWB + seg * 16,
                           g_a + (size_t)(row0 + r) * ND + k0 + seg * 8);
                CP_ASYNC16(dB + r * ROWB + seg * 16,
                           g_b + (size_t)(col0 + r) * ND + k0 + seg * 8);
            }
            CP_COMMIT();
        }

        const uint32_t bufA = sA0 + cur * STAGE_A + aoff;
        const uint32_t bufB = sB0 + cur * STAGE_B + boff;

#pragma unroll
        for (int ks = 0; ks < 4; ++ks) {        // four k16 steps per 64-chunk
            const uint32_t kb = ks * 32;        // 16 halves = 32 bytes
            uint32_t a[2][4], b[4][4];
#pragma unroll
            for (int mi = 0; mi < 2; ++mi)
                LDMATRIX_X4(a[mi][0], a[mi][1], a[mi][2], a[mi][3],
                            bufA + mi * (16 * ROWB) + kb);
#pragma unroll
            for (int nj = 0; nj < 4; ++nj)
                LDMATRIX_X4(b[nj][0], b[nj][1], b[nj][2], b[nj][3],
                            bufB + nj * (16 * ROWB) + kb);
#pragma unroll
            for (int mi = 0; mi < 2; ++mi)
#pragma unroll
                for (int nj = 0; nj < 4; ++nj) {
                    MMA_16816(acc[mi][nj * 2],     a[mi], &b[nj][0]);
                    MMA_16816(acc[mi][nj * 2 + 1], a[mi], &b[nj][2]);
                }
        }
    }

    // ---------------- fused epilogue ----------------
    const float tau = fminf(expf(log_tau[0]), 100.0f);
#pragma unroll
    for (int mi = 0; mi < 2; ++mi)
#pragma unroll
        for (int nj = 0; nj < 8; ++nj)
#pragma unroll
            for (int q = 0; q < 4; ++q) acc[mi][nj][q] *= tau;

    const int lrow = lane >> 2;
    const int lcol = (lane & 3) * 2;

    // diag extraction (only on diagonal tiles)
    if (bx == by) {
#pragma unroll
        for (int mi = 0; mi < 2; ++mi)
#pragma unroll
            for (int nj = 0; nj < 8; ++nj)
#pragma unroll
                for (int q = 0; q < 4; ++q) {
                    const int rl = wm * 32 + mi * 16 + ((q >> 1) << 3) + lrow;
                    const int cl = wn * 64 + nj * 8 + lcol + (q & 1);
                    if (rl == cl) g_diag[row0 + rl] = acc[mi][nj][q];
                }
    }

    // --- row partials: max+sum over this warp's 64 columns
#pragma unroll
    for (int mi = 0; mi < 2; ++mi)
#pragma unroll
        for (int h = 0; h < 2; ++h) {
            float m = NEG_BIG;
#pragma unroll
            for (int nj = 0; nj < 8; ++nj)
                m = fmaxf(m, fmaxf(acc[mi][nj][h * 2], acc[mi][nj][h * 2 + 1]));
            m = fmaxf(m, __shfl_xor_sync(0xffffffffu, m, 1));
            m = fmaxf(m, __shfl_xor_sync(0xffffffffu, m, 2));
            float s = 0.f;
#pragma unroll
            for (int nj = 0; nj < 8; ++nj)
                s += __expf(acc[mi][nj][h * 2] - m) +
                     __expf(acc[mi][nj][h * 2 + 1] - m);
            s += __shfl_xor_sync(0xffffffffu, s, 1);
            s += __shfl_xor_sync(0xffffffffu, s, 2);
            if ((lane & 3) == 0) {
                const int r = wm * 32 + mi * 16 + h * 8 + lrow;
                sm_rm[wn][r] = m;
                sm_rs[wn][r] = s;
            }
        }

    // --- col partials: max+sum over this warp's 32 rows
#pragma unroll
    for (int nj = 0; nj < 8; ++nj)
#pragma unroll
        for (int cc = 0; cc < 2; ++cc) {
            const float v0 = acc[0][nj][cc], v1 = acc[0][nj][2 + cc];
            const float v2 = acc[1][nj][cc], v3 = acc[1][nj][2 + cc];
            float m = fmaxf(fmaxf(v0, v1), fmaxf(v2, v3));
            m = fmaxf(m, __shfl_xor_sync(0xffffffffu, m, 4));
            m = fmaxf(m, __shfl_xor_sync(0xffffffffu, m, 8));
            m = fmaxf(m, __shfl_xor_sync(0xffffffffu, m, 16));
            float s = __expf(v0 - m) + __expf(v1 - m) +
                      __expf(v2 - m) + __expf(v3 - m);
            s += __shfl_xor_sync(0xffffffffu, s, 4);
            s += __shfl_xor_sync(0xffffffffu, s, 8);
            s += __shfl_xor_sync(0xffffffffu, s, 16);
            if (lane < 4) {
                const int cl = wn * 64 + nj * 8 + (lane & 3) * 2 + cc;
                sm_cm[wm][cl] = m;
                sm_cs[wm][cl] = s;
            }
        }

    __syncthreads();

    if (tid < BM) {
        const float m0 = sm_rm[0][tid], m1 = sm_rm[1][tid];
        const float m = fmaxf(m0, m1);
        const float s = sm_rs[0][tid] * __expf(m0 - m) +
                        sm_rs[1][tid] * __expf(m1 - m);
        g_rp_m[bx * NB + row0 + tid] = m;
        g_rp_s[bx * NB + row0 + tid] = s;

        float cm = NEG_BIG;
#pragma unroll
        for (int w = 0; w < 4; ++w) cm = fmaxf(cm, sm_cm[w][tid]);
        float cs = 0.f;
#pragma unroll
        for (int w = 0; w < 4; ++w) cs += sm_cs[w][tid] * __expf(sm_cm[w][tid] - cm);
        g_cp_m[by * NB + col0 + tid] = cm;
        g_cp_s[by * NB + col0 + tid] = cs;
    }
}

// ---------------------------------------------------------------------------
// K2: combine partials -> LSE -> loss, single kernel.
// 32 blocks: blocks 0..15 handle rows (and subtract diag), 16..31 handle cols.
// Last block (atomic ticket) sums the 32 per-block double partials in fixed
// order (deterministic), writes the scalar, and resets the ticket.
// ---------------------------------------------------------------------------
__global__ __launch_bounds__(256)
void combine_final_kernel(float* __restrict__ out)
{
    __shared__ double red[256];
    const int b   = blockIdx.x;
    const int t   = threadIdx.x;
    const int dir = b >> 4;                      // 0 = rows, 1 = cols
    const int i   = (b & 15) * 256 + t;

    const float* Pm = dir ? g_cp_m : g_rp_m;
    const float* Ps = dir ? g_cp_s : g_rp_s;

    float m = NEG_BIG;
#pragma unroll
    for (int c = 0; c < NBLK; ++c)
        m = fmaxf(m, Pm[c * NB + i]);
    float s = 0.f;
#pragma unroll
    for (int c = 0; c < NBLK; ++c)
        s += Ps[c * NB + i] * __expf(Pm[c * NB + i] - m);
    const float lse = m + logf(s);

    double term = 0.5 * (double)lse;
    if (dir == 0) term -= (double)g_diag[i];

    red[t] = term;
    __syncthreads();
    for (int k = 128; k > 0; k >>= 1) {
        if (t < k) red[t] += red[t + k];
        __syncthreads();
    }
    if (t == 0) {
        g_part[b] = red[0];
        __threadfence();
        const int done = atomicAdd(&g_ticket, 1);
        if (done == 31) {
            double sum = 0.0;
            volatile double* vp = g_part;
            for (int k = 0; k < 32; ++k) sum += vp[k];
            out[0] = (float)(sum / (double)NB);
            g_ticket = 0;    // reset for next graph replay
        }
    }
}

// ---------------------------------------------------------------------------
extern "C" void kernel_launch(void* const* d_in, const int* in_sizes, int n_in,
                              void* d_out, int out_size)
{
    const float* ftir    = (const float*)d_in[0];   // [4096, 512] f32
    const float* raman   = (const float*)d_in[1];   // [4096, 512] f32
    // d_in[2] = labels (int64) — unused
    const float* log_tau = (const float*)d_in[3];   // scalar f32

    cudaFuncSetAttribute(gemm_fused_kernel,
                         cudaFuncAttributeMaxDynamicSharedMemorySize, SM_DYN);

    convert_kernel<<<dim3(NB * ND / (256 * 8), 2), 256>>>(ftir, raman);
    gemm_fused_kernel<<<dim3(NB / BN, NB / BM), GTHREADS, SM_DYN>>>(log_tau);
    combine_final_kernel<<<32, 256>>>((float*)d_out);
}